// round 1
// baseline (speedup 1.0000x reference)
#include <cuda_runtime.h>
#include <cstdint>

// Bayer mosaic channel select:
//   out[b,i,j] = img[b, c, i, j]
//   c = 1 if (i+j) even; else 2 if i even; else 0
// For a fixed row i, output alternates between two channel planes:
//   i even: j even -> ch1, j odd -> ch2
//   i odd : j even -> ch0, j odd -> ch1
// Each thread produces one float4 (4 consecutive j), reading one float4 from
// each of the two relevant channel rows and interleaving lanes.

static constexpr int B = 8;
static constexpr int C = 3;
static constexpr int H = 2048;
static constexpr int W = 2048;

__global__ __launch_bounds__(256)
void bayer_kernel(const float* __restrict__ img, float* __restrict__ out) {
    // Flatten over (b, i, j/4)
    const int W4 = W / 4;                       // 512 float4 per row
    int64_t gid = (int64_t)blockIdx.x * blockDim.x + threadIdx.x;
    // gid in [0, B*H*W4)
    int j4 = (int)(gid % W4);
    int64_t bi = gid / W4;                      // b*H + i
    int i = (int)(bi % H);
    int b = (int)(bi / H);

    // Channels for this row
    int cA, cB;  // cA: even j, cB: odd j
    if ((i & 1) == 0) { cA = 1; cB = 2; }
    else              { cA = 0; cB = 1; }

    const int64_t plane = (int64_t)H * W;
    const int64_t row_base = (int64_t)b * C * plane + (int64_t)i * W + (int64_t)j4 * 4;

    const float4 a = *reinterpret_cast<const float4*>(img + row_base + (int64_t)cA * plane);
    const float4 bv = *reinterpret_cast<const float4*>(img + row_base + (int64_t)cB * plane);

    float4 o;
    o.x = a.x;   // j%4 == 0 (even)
    o.y = bv.y;  // odd
    o.z = a.z;   // even
    o.w = bv.w;  // odd

    const int64_t out_idx = ((int64_t)b * H + i) * W + (int64_t)j4 * 4;
    *reinterpret_cast<float4*>(out + out_idx) = o;
}

extern "C" void kernel_launch(void* const* d_in, const int* in_sizes, int n_in,
                              void* d_out, int out_size) {
    const float* img = (const float*)d_in[0];
    float* out = (float*)d_out;

    const int64_t total4 = (int64_t)B * H * (W / 4);   // 8,388,608 threads
    const int threads = 256;
    const int blocks = (int)((total4 + threads - 1) / threads);  // 32768
    bayer_kernel<<<blocks, threads>>>(img, out);
}